// round 2
// baseline (speedup 1.0000x reference)
#include <cuda_runtime.h>
#include <math.h>

#define N_TOK 65536      // B*T
#define DIM 64
#define KCODE 512
#define IN_DIM 256
#define CBP 68           // padded codebook row pitch (floats, 16B aligned, conflict-free)

// ---------------- scratch ----------------
__device__ float g_z[N_TOK * DIM];
__device__ float g_A[N_TOK];            // fl32 sequential sum of fl(z_d^2)
__device__ float g_B[KCODE];            // fl32 sequential sum of fl(e_d^2)
__device__ int g_idx[N_TOK];
__device__ unsigned int g_counts[KCODE];
__device__ float g_loss_part[2048];

// ---------------- init: zero counts + codebook norms (bit-exact) ----------
__global__ void k_init(const float* __restrict__ cb) {
    int k = threadIdx.x;
    if (k < KCODE) {
        g_counts[k] = 0u;
        const float* e = cb + (size_t)k * DIM;
        float s = 0.f;
        for (int d = 0; d < DIM; d++)
            s = __fadd_rn(s, __fmul_rn(e[d], e[d]));   // sequential, no contraction
        g_B[k] = s;
    }
}

// ---------------- encoder: bit-exact z = x @ enc_w ------------------------
// Per output element: single accumulator, sequential fmaf over i = 0..255.
// Block: 256 thr, 32 rows. Thread (r=tid>>3, l=tid&7) computes d in
// {4l..4l+3} and {32+4l..32+4l+3} (two conflict-free float4 groups).
__global__ void k_enc(const float* __restrict__ x, const float* __restrict__ w) {
    extern __shared__ float s[];
    float* ws = s;                      // 256*64 = 16384 floats
    float* xs = s + IN_DIM * DIM;       // 32*256 = 8192 floats
    int tid = threadIdx.x;

    const float4* wg = (const float4*)w;
    float4* w4 = (float4*)ws;
    #pragma unroll 4
    for (int i = tid; i < IN_DIM * DIM / 4; i += 256) w4[i] = wg[i];

    size_t rowbase = (size_t)blockIdx.x * 32;
    const float4* xg = (const float4*)(x + rowbase * IN_DIM);
    float4* x4 = (float4*)xs;
    #pragma unroll 4
    for (int i = tid; i < 32 * IN_DIM / 4; i += 256) x4[i] = xg[i];
    __syncthreads();

    int r = tid >> 3, l = tid & 7;
    int d0 = 4 * l, d1 = 32 + 4 * l;
    const float* xr = xs + r * IN_DIM;
    float a0 = 0.f, a1 = 0.f, a2 = 0.f, a3 = 0.f;
    float b0 = 0.f, b1 = 0.f, b2 = 0.f, b3 = 0.f;
    #pragma unroll 8
    for (int i = 0; i < IN_DIM; i++) {
        float xv = xr[i];
        float4 w0 = *(const float4*)(ws + i * DIM + d0);
        float4 w1 = *(const float4*)(ws + i * DIM + d1);
        a0 = fmaf(xv, w0.x, a0); a1 = fmaf(xv, w0.y, a1);
        a2 = fmaf(xv, w0.z, a2); a3 = fmaf(xv, w0.w, a3);
        b0 = fmaf(xv, w1.x, b0); b1 = fmaf(xv, w1.y, b1);
        b2 = fmaf(xv, w1.z, b2); b3 = fmaf(xv, w1.w, b3);
    }
    size_t row = rowbase + r;
    float4 o0; o0.x = a0; o0.y = a1; o0.z = a2; o0.w = a3;
    float4 o1; o1.x = b0; o1.y = b1; o1.z = b2; o1.w = b3;
    *(float4*)(g_z + row * DIM + d0) = o0;
    *(float4*)(g_z + row * DIM + d1) = o1;

    // ---- A[n] = sequential fl-sum of fl(z_d^2), bit-exact ----
    __syncthreads();                    // all xs reads done; reuse as zs (pitch 65)
    float* zsp = xs;
    zsp[r * 65 + d0 + 0] = a0; zsp[r * 65 + d0 + 1] = a1;
    zsp[r * 65 + d0 + 2] = a2; zsp[r * 65 + d0 + 3] = a3;
    zsp[r * 65 + d1 + 0] = b0; zsp[r * 65 + d1 + 1] = b1;
    zsp[r * 65 + d1 + 2] = b2; zsp[r * 65 + d1 + 3] = b3;
    __syncthreads();
    if (tid < 32) {
        const float* zr = zsp + tid * 65;
        float acc = 0.f;
        for (int d = 0; d < DIM; d++)
            acc = __fadd_rn(acc, __fmul_rn(zr[d], zr[d]));
        g_A[rowbase + tid] = acc;
    }
}

// ---------------- VQ: dist = fl(fl(A+B_k) - (2z).e_k), first-index argmin --
// Block: 256 thr, 32 tokens, 8 lanes/token; lane l handles k = l, l+8, ...
__global__ void k_vq(const float* __restrict__ cb) {
    extern __shared__ float s[];
    float* cbs = s;                          // 512*68
    float* zs  = cbs + KCODE * CBP;          // 32*64
    float* Bs  = zs + 32 * DIM;              // 512
    float* As  = Bs + KCODE;                 // 32
    float* larr = As + 32;                   // 32
    int tid = threadIdx.x;
    size_t rowbase = (size_t)blockIdx.x * 32;

    // load codebook (padded rows, 16B-aligned)
    const float4* cg = (const float4*)cb;
    for (int i = tid; i < KCODE * (DIM / 4); i += 256) {
        int row = i >> 4, q = i & 15;
        *(float4*)(cbs + row * CBP + q * 4) = cg[i];
    }
    // load z rows
    const float4* zg = (const float4*)(g_z + rowbase * DIM);
    float4* zs4 = (float4*)zs;
    #pragma unroll 2
    for (int i = tid; i < 32 * (DIM / 4); i += 256) zs4[i] = zg[i];
    for (int k = tid; k < KCODE; k += 256) Bs[k] = g_B[k];
    if (tid < 32) As[tid] = g_A[rowbase + tid];
    __syncthreads();

    int tok = tid >> 3, l = tid & 7;
    float4 zf[16];
    const float4* zrow = (const float4*)(zs + tok * DIM);
    #pragma unroll
    for (int q = 0; q < 16; q++) {
        float4 v = zrow[q];
        v.x *= 2.0f; v.y *= 2.0f; v.z *= 2.0f; v.w *= 2.0f;  // fl(2z): exact
        zf[q] = v;
    }
    float a = As[tok];

    float best = 3.4e38f;
    int bidx = 0;
    for (int j = 0; j < 64; j += 4) {
        const float4* p0 = (const float4*)(cbs + (8 * (j + 0) + l) * CBP);
        const float4* p1 = (const float4*)(cbs + (8 * (j + 1) + l) * CBP);
        const float4* p2 = (const float4*)(cbs + (8 * (j + 2) + l) * CBP);
        const float4* p3 = (const float4*)(cbs + (8 * (j + 3) + l) * CBP);
        float m0 = 0.f, m1 = 0.f, m2 = 0.f, m3 = 0.f;
        #pragma unroll
        for (int q = 0; q < 16; q++) {
            float4 z4 = zf[q];
            float4 e0 = p0[q], e1 = p1[q], e2 = p2[q], e3 = p3[q];
            m0 = fmaf(z4.x, e0.x, m0); m0 = fmaf(z4.y, e0.y, m0);
            m0 = fmaf(z4.z, e0.z, m0); m0 = fmaf(z4.w, e0.w, m0);
            m1 = fmaf(z4.x, e1.x, m1); m1 = fmaf(z4.y, e1.y, m1);
            m1 = fmaf(z4.z, e1.z, m1); m1 = fmaf(z4.w, e1.w, m1);
            m2 = fmaf(z4.x, e2.x, m2); m2 = fmaf(z4.y, e2.y, m2);
            m2 = fmaf(z4.z, e2.z, m2); m2 = fmaf(z4.w, e2.w, m2);
            m3 = fmaf(z4.x, e3.x, m3); m3 = fmaf(z4.y, e3.y, m3);
            m3 = fmaf(z4.z, e3.z, m3); m3 = fmaf(z4.w, e3.w, m3);
        }
        float dd[4];
        dd[0] = __fsub_rn(__fadd_rn(a, Bs[8 * (j + 0) + l]), m0);
        dd[1] = __fsub_rn(__fadd_rn(a, Bs[8 * (j + 1) + l]), m1);
        dd[2] = __fsub_rn(__fadd_rn(a, Bs[8 * (j + 2) + l]), m2);
        dd[3] = __fsub_rn(__fadd_rn(a, Bs[8 * (j + 3) + l]), m3);
        #pragma unroll
        for (int t = 0; t < 4; t++) {
            int k = 8 * (j + t) + l;
            if (dd[t] < best) { best = dd[t]; bidx = k; }   // strict <: first occurrence
        }
    }

    // lexicographic (dist, index) min across the 8 lanes == global first-index argmin
    #pragma unroll
    for (int off = 4; off >= 1; off >>= 1) {
        float od = __shfl_xor_sync(0xffffffffu, best, off);
        int oi = __shfl_xor_sync(0xffffffffu, bidx, off);
        if (od < best || (od == best && oi < bidx)) { best = od; bidx = oi; }
    }

    if (l == 0) {
        size_t n = rowbase + tok;
        g_idx[n] = bidx;
        atomicAdd(&g_counts[bidx], 1u);
        // loss contribution (tolerance 1e-3; any fp32 order fine)
        const float* e = cbs + bidx * CBP;
        const float* zr = zs + tok * DIM;
        float ls = 0.f;
        #pragma unroll
        for (int d = 0; d < DIM; d++) {
            float df = e[d] - zr[d];
            ls = fmaf(df, df, ls);
        }
        larr[tok] = ls;
    }
    __syncthreads();
    if (tid == 0) {
        float acc = 0.f;
        #pragma unroll
        for (int t = 0; t < 32; t++) acc += larr[t];
        g_loss_part[blockIdx.x] = acc;
    }
}

// ---------------- decoder: out = quantized_st @ dec_w ---------------------
// quantized_st = fl(z + fl(q - z)); output at out (4B-aligned only).
__global__ void k_dec(const float* __restrict__ cb, const float* __restrict__ dw,
                      float* __restrict__ out) {
    extern __shared__ float s[];
    float* ws = s;                  // 64*256
    float* qs = s + DIM * IN_DIM;   // 4*64
    int tid = threadIdx.x;

    const float4* wg = (const float4*)dw;
    float4* w4 = (float4*)ws;
    #pragma unroll 4
    for (int i = tid; i < DIM * IN_DIM / 4; i += 256) w4[i] = wg[i];

    size_t rowbase = (size_t)blockIdx.x * 64;
    int r = tid >> 6;      // 0..3
    int iq = tid & 63;     // which float4 of IN_DIM output

    for (int c = 0; c < 16; c++) {
        __syncthreads();
        {
            int rr = tid >> 6, dd = tid & 63;
            size_t n = rowbase + (size_t)c * 4 + rr;
            float qv = cb[(size_t)g_idx[n] * DIM + dd];
            float zv = g_z[n * DIM + dd];
            qs[tid] = __fadd_rn(zv, __fsub_rn(qv, zv));  // straight-through in fp32
        }
        __syncthreads();

        const float* qr = qs + r * DIM;
        float ax = 0.f, ay = 0.f, az = 0.f, aw = 0.f;
        #pragma unroll 8
        for (int d = 0; d < DIM; d++) {
            float qv = qr[d];
            float4 wv = ((const float4*)(ws + d * IN_DIM))[iq];
            ax = fmaf(qv, wv.x, ax);
            ay = fmaf(qv, wv.y, ay);
            az = fmaf(qv, wv.z, az);
            aw = fmaf(qv, wv.w, aw);
        }
        size_t n = rowbase + (size_t)c * 4 + r;
        float* o = out + n * IN_DIM + iq * 4;
        o[0] = ax; o[1] = ay; o[2] = az; o[3] = aw;
    }
}

// ---------------- final: loss + perplexity --------------------------------
__global__ void k_final(float* __restrict__ out, int out_size) {
    __shared__ float red[512];
    int tid = threadIdx.x;

    unsigned int cnt = g_counts[tid];
    float p = (float)cnt * (1.0f / (float)N_TOK);
    red[tid] = p * logf(p + 1e-10f);
    __syncthreads();
    for (int st = 256; st > 0; st >>= 1) {
        if (tid < st) red[tid] += red[tid + st];
        __syncthreads();
    }
    float ent = -red[0];
    __syncthreads();

    float acc = 0.f;
    #pragma unroll
    for (int j = 0; j < 4; j++) acc += g_loss_part[tid + 512 * j];
    red[tid] = acc;
    __syncthreads();
    for (int st = 256; st > 0; st >>= 1) {
        if (tid < st) red[tid] += red[tid + st];
        __syncthreads();
    }
    if (tid == 0) {
        out[0] = 1.25f * red[0] / (float)((size_t)N_TOK * DIM);
        out[out_size - 1] = expf(ent);
    }
}

// ---------------- launch ----------------
extern "C" void kernel_launch(void* const* d_in, const int* in_sizes, int n_in,
                              void* d_out, int out_size) {
    const float* x = nullptr;
    const float* enc_w = nullptr;
    const float* dec_w = nullptr;
    const float* cb = nullptr;
    for (int i = 0; i < n_in; i++) {
        const float* p = (const float*)d_in[i];
        int sz = in_sizes[i];
        if (sz == N_TOK * IN_DIM) x = p;
        else if (sz == KCODE * DIM) cb = p;
        else if (sz == IN_DIM * DIM) { if (!enc_w) enc_w = p; else dec_w = p; }
    }

    const int SM_ENC = (IN_DIM * DIM + 32 * IN_DIM) * 4;                     // 98304
    const int SM_VQ  = (KCODE * CBP + 32 * DIM + KCODE + 32 + 32) * 4;       // ~149KB
    const int SM_DEC = (DIM * IN_DIM + 4 * DIM) * 4;                         // 66560
    cudaFuncSetAttribute(k_enc, cudaFuncAttributeMaxDynamicSharedMemorySize, SM_ENC);
    cudaFuncSetAttribute(k_vq,  cudaFuncAttributeMaxDynamicSharedMemorySize, SM_VQ);
    cudaFuncSetAttribute(k_dec, cudaFuncAttributeMaxDynamicSharedMemorySize, SM_DEC);

    float* out = (float*)d_out;

    k_init<<<1, 512>>>(cb);
    k_enc<<<N_TOK / 32, 256, SM_ENC>>>(x, enc_w);
    k_vq<<<N_TOK / 32, 256, SM_VQ>>>(cb);
    k_dec<<<N_TOK / 64, 256, SM_DEC>>>(cb, dec_w, out + 1);
    k_final<<<1, 512>>>(out, out_size);
}

// round 4
// speedup vs baseline: 1.9810x; 1.9810x over previous
#include <cuda_runtime.h>
#include <math.h>

#define N_TOK 65536
#define DIM 64
#define KCODE 512
#define IN_DIM 256

// ---------------- device scratch (16B-aligned: accessed via float4) -------
__device__ __align__(16) float g_zT[DIM * N_TOK];        // 2*z transposed [d][n]
__device__ __align__(16) float g_A[N_TOK];               // bit-exact ||z||^2
__device__ __align__(16) float g_B[KCODE];               // bit-exact ||e||^2
__device__ __align__(16) float g_eT[DIM * KCODE];        // codebook transposed
__device__ __align__(16) float g_table[KCODE * IN_DIM];  // cb @ dec_w
__device__ __align__(16) int g_idx[N_TOK];
__device__ __align__(16) unsigned int g_counts[KCODE];
__device__ __align__(16) float g_loss_part[1024];

// ---------------- init: counts=0, B[k] bit-exact ----------------
__global__ void k_init(const float* __restrict__ cb) {
    int k = threadIdx.x;
    if (k < KCODE) {
        g_counts[k] = 0u;
        const float* e = cb + (size_t)k * DIM;
        float s = 0.f;
        for (int d = 0; d < DIM; d++)
            s = __fadd_rn(s, __fmul_rn(e[d], e[d]));
        g_B[k] = s;
    }
}

// ---------------- transpose codebook: eT[d][k] = cb[k][d] ----------------
__global__ void k_transpose(const float* __restrict__ cb) {
    int d = blockIdx.x;                 // 0..63
    int t = threadIdx.x;                // 256
    g_eT[d * KCODE + t]       = cb[(size_t)t * DIM + d];
    g_eT[d * KCODE + 256 + t] = cb[(size_t)(256 + t) * DIM + d];
}

// ---------------- table[k][i] = sum_d cb[k][d] * dec_w[d][i] ----------------
__global__ void k_table(const float* __restrict__ cb, const float* __restrict__ dw) {
    __shared__ float e[DIM];
    int k = blockIdx.x, tid = threadIdx.x;
    if (tid < DIM) e[tid] = cb[(size_t)k * DIM + tid];
    __syncthreads();
    float acc = 0.f;
    #pragma unroll 8
    for (int d = 0; d < DIM; d++)
        acc = fmaf(e[d], dw[d * IN_DIM + tid], acc);
    g_table[(size_t)k * IN_DIM + tid] = acc;
}

// ---------------- encoder: z = x @ enc_w (bit-exact chains) ---------------
// 256 thr, 128 rows/block. Thread (rg=tid>>3, cg=tid&7): rows 4rg..+3, cols 8cg..+7.
#define XP 260                      // x smem pitch
__global__ void k_enc(const float* __restrict__ x, const float* __restrict__ w) {
    extern __shared__ float s[];
    float* ws = s;                  // [256][64]
    float* xs = s + IN_DIM * DIM;   // [128][XP]
    int tid = threadIdx.x;
    size_t rowbase = (size_t)blockIdx.x * 128;

    {   // w: linear float4 copy
        const float4* wg = (const float4*)w;
        float4* w4 = (float4*)ws;
        #pragma unroll 4
        for (int i = tid; i < IN_DIM * DIM / 4; i += 256) w4[i] = wg[i];
        // x tile: 128 rows x 64 float4 = 8192 float4
        const float4* xg = (const float4*)(x + rowbase * IN_DIM);
        #pragma unroll 4
        for (int it = 0; it < 32; it++) {
            int idx = it * 256 + tid;
            int r = idx >> 6, q = idx & 63;
            *(float4*)(xs + r * XP + 4 * q) = xg[(size_t)r * 64 + q];
        }
    }
    __syncthreads();

    int rg = tid >> 3, cg = tid & 7;
    float acc[4][8];
    #pragma unroll
    for (int a = 0; a < 4; a++)
        #pragma unroll
        for (int b = 0; b < 8; b++) acc[a][b] = 0.f;

    const float* xr0 = xs + (4 * rg + 0) * XP;
    const float* xr1 = xs + (4 * rg + 1) * XP;
    const float* xr2 = xs + (4 * rg + 2) * XP;
    const float* xr3 = xs + (4 * rg + 3) * XP;

    #pragma unroll 4
    for (int i = 0; i < IN_DIM; i++) {
        float x0 = xr0[i], x1 = xr1[i], x2 = xr2[i], x3 = xr3[i];
        float4 wa = *(const float4*)(ws + i * DIM + 8 * cg);
        float4 wb = *(const float4*)(ws + i * DIM + 8 * cg + 4);
        float wv[8] = {wa.x, wa.y, wa.z, wa.w, wb.x, wb.y, wb.z, wb.w};
        #pragma unroll
        for (int b = 0; b < 8; b++) {
            acc[0][b] = fmaf(x0, wv[b], acc[0][b]);
            acc[1][b] = fmaf(x1, wv[b], acc[1][b]);
            acc[2][b] = fmaf(x2, wv[b], acc[2][b]);
            acc[3][b] = fmaf(x3, wv[b], acc[3][b]);
        }
    }

    // store 2*z transposed to global (exact doubling)
    #pragma unroll
    for (int b = 0; b < 8; b++) {
        float4 v;
        v.x = 2.0f * acc[0][b]; v.y = 2.0f * acc[1][b];
        v.z = 2.0f * acc[2][b]; v.w = 2.0f * acc[3][b];
        *(float4*)(g_zT + (size_t)(8 * cg + b) * N_TOK + rowbase + 4 * rg) = v;
    }

    // A[n]: bit-exact sequential sum of z_d^2 (reuse ws region, pitch 65)
    __syncthreads();
    float* zs = s;                  // [128][65] = 8320 floats, fits in ws region
    #pragma unroll
    for (int a = 0; a < 4; a++)
        #pragma unroll
        for (int b = 0; b < 8; b++)
            zs[(4 * rg + a) * 65 + 8 * cg + b] = acc[a][b];
    __syncthreads();
    if (tid < 128) {
        const float* zr = zs + tid * 65;
        float sA = 0.f;
        for (int d = 0; d < DIM; d++)
            sA = __fadd_rn(sA, __fmul_rn(zr[d], zr[d]));
        g_A[rowbase + tid] = sA;
    }
}

// ---------------- VQ: dist = fl(fl(A+B)-m), first-index argmin -------------
// 256 thr, 64 tokens/block. Thread (tg=tid>>4, cg=tid&15): tokens 4tg..+3,
// codes {pass*128 + 8cg .. +7} over 4 passes.
__global__ void k_vq() {
    extern __shared__ float s[];
    float* eT = s;                       // [64][512]
    float* zs = s + DIM * KCODE;         // [64][64]
    float* Bs = zs + DIM * DIM;          // [512]
    float* As = Bs + KCODE;              // [64]
    float* lred = As + DIM;              // [16]
    int tid = threadIdx.x;
    size_t base = (size_t)blockIdx.x * 64;

    {   // eT: linear float4 copy (pre-transposed in global)
        const float4* eg = (const float4*)g_eT;
        float4* e4 = (float4*)eT;
        #pragma unroll 4
        for (int i = tid; i < DIM * KCODE / 4; i += 256) e4[i] = eg[i];
        // zs[d][tok]: 64 rows x 16 float4 = 1024 float4  (FIXED: 4 iters, not 16)
        #pragma unroll
        for (int it = 0; it < 4; it++) {
            int idx = it * 256 + tid;
            int d = idx >> 4, q = idx & 15;
            *(float4*)(zs + d * 64 + 4 * q) =
                *(const float4*)(g_zT + (size_t)d * N_TOK + base + 4 * q);
        }
        for (int k = tid; k < KCODE; k += 256) Bs[k] = g_B[k];
        if (tid < 64) As[tid] = g_A[base + tid];
    }
    __syncthreads();

    int tg = tid >> 4, cg = tid & 15;
    float best[4];
    int bidx[4];
    #pragma unroll
    for (int t = 0; t < 4; t++) { best[t] = 3.4e38f; bidx[t] = 0; }
    float a0 = As[4 * tg + 0], a1 = As[4 * tg + 1];
    float a2 = As[4 * tg + 2], a3 = As[4 * tg + 3];

    #pragma unroll
    for (int pass = 0; pass < 4; pass++) {
        float m[4][8];
        #pragma unroll
        for (int t = 0; t < 4; t++)
            #pragma unroll
            for (int c = 0; c < 8; c++) m[t][c] = 0.f;

        const float* ebase = eT + pass * 128 + 8 * cg;
        #pragma unroll 4
        for (int d = 0; d < DIM; d++) {
            float4 zf = *(const float4*)(zs + d * 64 + 4 * tg);   // already 2*z
            float4 ea = *(const float4*)(ebase + d * KCODE);
            float4 eb = *(const float4*)(ebase + d * KCODE + 4);
            float ev[8] = {ea.x, ea.y, ea.z, ea.w, eb.x, eb.y, eb.z, eb.w};
            #pragma unroll
            for (int c = 0; c < 8; c++) {
                m[0][c] = fmaf(zf.x, ev[c], m[0][c]);
                m[1][c] = fmaf(zf.y, ev[c], m[1][c]);
                m[2][c] = fmaf(zf.z, ev[c], m[2][c]);
                m[3][c] = fmaf(zf.w, ev[c], m[3][c]);
            }
        }
        float av[4] = {a0, a1, a2, a3};
        #pragma unroll
        for (int c = 0; c < 8; c++) {
            int k = pass * 128 + 8 * cg + c;
            float bk = Bs[k];
            #pragma unroll
            for (int t = 0; t < 4; t++) {
                float dd = __fsub_rn(__fadd_rn(av[t], bk), m[t][c]);
                if (dd < best[t]) { best[t] = dd; bidx[t] = k; }
            }
        }
    }

    // lexicographic (dist, index) min across the 16 cg lanes
    #pragma unroll
    for (int off = 8; off >= 1; off >>= 1) {
        #pragma unroll
        for (int t = 0; t < 4; t++) {
            float od = __shfl_xor_sync(0xffffffffu, best[t], off);
            int oi = __shfl_xor_sync(0xffffffffu, bidx[t], off);
            if (od < best[t] || (od == best[t] && oi < bidx[t])) {
                best[t] = od; bidx[t] = oi;
            }
        }
    }

    if (cg == 0) {
        float ls = 0.f;
        #pragma unroll
        for (int t = 0; t < 4; t++) {
            size_t n = base + 4 * tg + t;
            g_idx[n] = bidx[t];
            atomicAdd(&g_counts[bidx[t]], 1u);
            ls += best[t];          // dist == ||z - e||^2 (loose tolerance)
        }
        lred[tg] = ls;
    }
    __syncthreads();
    if (tid == 0) {
        float acc = 0.f;
        #pragma unroll
        for (int t = 0; t < 16; t++) acc += lred[t];
        g_loss_part[blockIdx.x] = acc;
    }
}

// ---------------- gather: out[n][i] = table[idx[n]][i] ---------------------
__global__ void k_gather(float* __restrict__ out) {
    __shared__ int sidx[32];
    int tid = threadIdx.x;
    size_t base = (size_t)blockIdx.x * 32;
    if (tid < 32) sidx[tid] = g_idx[base + tid];
    __syncthreads();
    int rr = tid >> 6, q = tid & 63;
    #pragma unroll
    for (int j = 0; j < 8; j++) {
        int t = j * 4 + rr;
        float4 v = *(const float4*)(g_table + (size_t)sidx[t] * IN_DIM + 4 * q);
        float* o = out + (base + t) * IN_DIM + 4 * q;
        o[0] = v.x; o[1] = v.y; o[2] = v.z; o[3] = v.w;
    }
}

// ---------------- final: loss + perplexity ---------------------------------
__global__ void k_final(float* __restrict__ out, int out_size) {
    __shared__ float red[512];
    int tid = threadIdx.x;

    unsigned int cnt = g_counts[tid];
    float p = (float)cnt * (1.0f / (float)N_TOK);
    red[tid] = p * logf(p + 1e-10f);
    __syncthreads();
    for (int st = 256; st > 0; st >>= 1) {
        if (tid < st) red[tid] += red[tid + st];
        __syncthreads();
    }
    float ent = -red[0];
    __syncthreads();

    red[tid] = g_loss_part[tid] + g_loss_part[tid + 512];
    __syncthreads();
    for (int st = 256; st > 0; st >>= 1) {
        if (tid < st) red[tid] += red[tid + st];
        __syncthreads();
    }
    if (tid == 0) {
        out[0] = 1.25f * red[0] / (float)((size_t)N_TOK * DIM);
        out[out_size - 1] = expf(ent);
    }
}

// ---------------- launch ----------------
extern "C" void kernel_launch(void* const* d_in, const int* in_sizes, int n_in,
                              void* d_out, int out_size) {
    const float* x = nullptr;
    const float* enc_w = nullptr;
    const float* dec_w = nullptr;
    const float* cb = nullptr;
    for (int i = 0; i < n_in; i++) {
        const float* p = (const float*)d_in[i];
        int sz = in_sizes[i];
        if (sz == N_TOK * IN_DIM) x = p;
        else if (sz == KCODE * DIM) cb = p;
        else if (sz == IN_DIM * DIM) { if (!enc_w) enc_w = p; else dec_w = p; }
    }

    const int SM_ENC = (IN_DIM * DIM + 128 * XP) * 4;                        // 198656
    const int SM_VQ  = (DIM * KCODE + DIM * DIM + KCODE + DIM + 16) * 4;     // 149824
    cudaFuncSetAttribute(k_enc, cudaFuncAttributeMaxDynamicSharedMemorySize, SM_ENC);
    cudaFuncSetAttribute(k_vq,  cudaFuncAttributeMaxDynamicSharedMemorySize, SM_VQ);

    float* out = (float*)d_out;

    k_init<<<1, 512>>>(cb);
    k_transpose<<<64, 256>>>(cb);
    k_table<<<512, 256>>>(cb, dec_w);
    k_enc<<<N_TOK / 128, 256, SM_ENC>>>(x, enc_w);
    k_vq<<<N_TOK / 64, 256, SM_VQ>>>();
    k_gather<<<N_TOK / 32, 256>>>(out + 1);
    k_final<<<1, 512>>>(out, out_size);
}

// round 5
// speedup vs baseline: 2.7586x; 1.3926x over previous
#include <cuda_runtime.h>
#include <math.h>

#define N_TOK 65536
#define DIM 64
#define KCODE 512
#define IN_DIM 256

// ---------------- device scratch (16B-aligned) ----------------
__device__ __align__(16) float g_zT[DIM * N_TOK];        // 2*z transposed [d][n]
__device__ __align__(16) float g_A[N_TOK];               // bit-exact ||z||^2
__device__ __align__(16) float g_B[KCODE];               // bit-exact ||e||^2
__device__ __align__(16) float g_eT[DIM * KCODE];        // codebook transposed
__device__ __align__(16) float g_table[KCODE * IN_DIM];  // cb @ dec_w
__device__ __align__(16) int g_idx[N_TOK];
__device__ __align__(16) unsigned int g_counts[KCODE];
__device__ __align__(16) float g_loss_part[512];

// ---------------- setup: transpose cb, zero counts, B[k] bit-exact --------
__global__ void k_setup(const float* __restrict__ cb) {
    int b = blockIdx.x, t = threadIdx.x;
    if (b < 64) {                       // transpose: eT[d][k] = cb[k][d]
        g_eT[b * KCODE + t]       = cb[(size_t)t * DIM + b];
        g_eT[b * KCODE + 256 + t] = cb[(size_t)(256 + t) * DIM + b];
    } else {                            // b == 64: counts + norms
        int k0 = t, k1 = t + 256;
        g_counts[k0] = 0u; g_counts[k1] = 0u;
        const float* e0 = cb + (size_t)k0 * DIM;
        const float* e1 = cb + (size_t)k1 * DIM;
        float s0 = 0.f, s1 = 0.f;
        for (int d = 0; d < DIM; d++) {
            s0 = __fadd_rn(s0, __fmul_rn(e0[d], e0[d]));
            s1 = __fadd_rn(s1, __fmul_rn(e1[d], e1[d]));
        }
        g_B[k0] = s0; g_B[k1] = s1;
    }
}

// ---------------- table[k][i] = sum_d cb[k][d] * dec_w[d][i] ----------------
__global__ void k_table(const float* __restrict__ cb, const float* __restrict__ dw) {
    __shared__ float e[DIM];
    int k = blockIdx.x, tid = threadIdx.x;
    if (tid < DIM) e[tid] = cb[(size_t)k * DIM + tid];
    __syncthreads();
    float acc = 0.f;
    #pragma unroll 8
    for (int d = 0; d < DIM; d++)
        acc = fmaf(e[d], dw[d * IN_DIM + tid], acc);
    g_table[(size_t)k * IN_DIM + tid] = acc;
}

// ---------------- encoder: z = x @ enc_w (bit-exact chains) ---------------
// 256 thr, 128 rows/block, x staged in 4 chunks of 64 i -> 98.8KB smem, 2 CTA/SM.
// Thread (rg=tid>>3, cg=tid&7): rows 4rg..+3, cols {4cg..+3, 32+4cg..+3}.
#define XCH 64                       // i per chunk
#define XPC 68                       // chunk pitch (floats)
__global__ void __launch_bounds__(256, 2)
k_enc(const float* __restrict__ x, const float* __restrict__ w) {
    extern __shared__ float s[];
    float* ws = s;                   // [256][64] = 64KB
    float* xs = s + IN_DIM * DIM;    // [128][XPC] = 34.8KB
    int tid = threadIdx.x;
    size_t rowbase = (size_t)blockIdx.x * 128;

    {   // w: linear float4 copy (once)
        const float4* wg = (const float4*)w;
        float4* w4 = (float4*)ws;
        #pragma unroll 4
        for (int i = tid; i < IN_DIM * DIM / 4; i += 256) w4[i] = wg[i];
    }

    int rg = tid >> 3, cg = tid & 7;
    float acc[4][8];
    #pragma unroll
    for (int a = 0; a < 4; a++)
        #pragma unroll
        for (int b = 0; b < 8; b++) acc[a][b] = 0.f;

    const float4* xg = (const float4*)(x + rowbase * IN_DIM);

    for (int c = 0; c < 4; c++) {
        __syncthreads();
        // load x chunk: 128 rows x 16 float4
        #pragma unroll
        for (int it = 0; it < 8; it++) {
            int idx = it * 256 + tid;
            int r = idx >> 4, q = idx & 15;
            *(float4*)(xs + r * XPC + 4 * q) = xg[(size_t)r * 64 + 16 * c + q];
        }
        __syncthreads();

        const float* xr0 = xs + (4 * rg + 0) * XPC;
        const float* xr1 = xs + (4 * rg + 1) * XPC;
        const float* xr2 = xs + (4 * rg + 2) * XPC;
        const float* xr3 = xs + (4 * rg + 3) * XPC;

        #pragma unroll
        for (int i4 = 0; i4 < XCH / 4; i4++) {
            float4 xv0 = *(const float4*)(xr0 + 4 * i4);
            float4 xv1 = *(const float4*)(xr1 + 4 * i4);
            float4 xv2 = *(const float4*)(xr2 + 4 * i4);
            float4 xv3 = *(const float4*)(xr3 + 4 * i4);
            #pragma unroll
            for (int j = 0; j < 4; j++) {
                int i = XCH * c + 4 * i4 + j;
                float4 wa = *(const float4*)(ws + i * DIM + 4 * cg);
                float4 wb = *(const float4*)(ws + i * DIM + 32 + 4 * cg);
                float wv[8] = {wa.x, wa.y, wa.z, wa.w, wb.x, wb.y, wb.z, wb.w};
                float x0 = ((const float*)&xv0)[j];
                float x1 = ((const float*)&xv1)[j];
                float x2 = ((const float*)&xv2)[j];
                float x3 = ((const float*)&xv3)[j];
                #pragma unroll
                for (int b = 0; b < 8; b++) {
                    acc[0][b] = fmaf(x0, wv[b], acc[0][b]);
                    acc[1][b] = fmaf(x1, wv[b], acc[1][b]);
                    acc[2][b] = fmaf(x2, wv[b], acc[2][b]);
                    acc[3][b] = fmaf(x3, wv[b], acc[3][b]);
                }
            }
        }
    }

    // store 2*z transposed (exact doubling); col(b) = b<4 ? 4cg+b : 32+4cg+b-4
    #pragma unroll
    for (int b = 0; b < 8; b++) {
        int col = (b < 4) ? (4 * cg + b) : (32 + 4 * cg + (b - 4));
        float4 v;
        v.x = 2.0f * acc[0][b]; v.y = 2.0f * acc[1][b];
        v.z = 2.0f * acc[2][b]; v.w = 2.0f * acc[3][b];
        *(float4*)(g_zT + (size_t)col * N_TOK + rowbase + 4 * rg) = v;
    }

    // A[n]: bit-exact sequential sum of z_d^2 (reuse xs region, pitch 65)
    __syncthreads();
    float* zs = xs;                  // 128*65 = 8320 <= 128*68
    #pragma unroll
    for (int a = 0; a < 4; a++)
        #pragma unroll
        for (int b = 0; b < 8; b++) {
            int col = (b < 4) ? (4 * cg + b) : (32 + 4 * cg + (b - 4));
            zs[(4 * rg + a) * 65 + col] = acc[a][b];
        }
    __syncthreads();
    if (tid < 128) {
        const float* zr = zs + tid * 65;
        float sA = 0.f;
        for (int d = 0; d < DIM; d++)
            sA = __fadd_rn(sA, __fmul_rn(zr[d], zr[d]));
        g_A[rowbase + tid] = sA;
    }
}

// ---------------- VQ: dist = fl(fl(A+B)-m), first-index argmin -------------
// 512 thr, 128 tokens/block. Thread (tg=tid>>4 in 0..31, cg=tid&15):
// tokens 4tg..+3; per pass p codes {p*128+4cg+r, p*128+64+4cg+r}, r=0..3.
__global__ void __launch_bounds__(512, 1) k_vq() {
    extern __shared__ float s[];
    float* eT = s;                       // [64][512] = 131KB
    float* zs = s + DIM * KCODE;         // [64][128] = 32KB
    float* Bs = zs + DIM * 128;          // [512]
    float* As = Bs + KCODE;              // [128]
    float* lred = As + 128;              // [32]
    int tid = threadIdx.x;
    size_t base = (size_t)blockIdx.x * 128;

    {   // eT: linear float4 copy
        const float4* eg = (const float4*)g_eT;
        float4* e4 = (float4*)eT;
        #pragma unroll 4
        for (int i = tid; i < DIM * KCODE / 4; i += 512) e4[i] = eg[i];
        // zs[d][tok]: 64 x 32 float4 = 2048 float4
        #pragma unroll
        for (int it = 0; it < 4; it++) {
            int idx = it * 512 + tid;
            int d = idx >> 5, q = idx & 31;
            *(float4*)(zs + d * 128 + 4 * q) =
                *(const float4*)(g_zT + (size_t)d * N_TOK + base + 4 * q);
        }
        if (tid < KCODE) Bs[tid] = g_B[tid];
        if (tid < 128) As[tid] = g_A[base + tid];
    }
    __syncthreads();

    int tg = tid >> 4, cg = tid & 15;
    float best[4];
    int bidx[4];
    #pragma unroll
    for (int t = 0; t < 4; t++) { best[t] = 3.4e38f; bidx[t] = 0; }
    float a0 = As[4 * tg + 0], a1 = As[4 * tg + 1];
    float a2 = As[4 * tg + 2], a3 = As[4 * tg + 3];

    #pragma unroll
    for (int pass = 0; pass < 4; pass++) {
        float m[4][8];
        #pragma unroll
        for (int t = 0; t < 4; t++)
            #pragma unroll
            for (int c = 0; c < 8; c++) m[t][c] = 0.f;

        const float* e1 = eT + pass * 128 + 4 * cg;        // codes p*128+4cg+r
        const float* e2 = eT + pass * 128 + 64 + 4 * cg;   // codes p*128+64+4cg+r
        #pragma unroll 4
        for (int d = 0; d < DIM; d++) {
            float4 zf = *(const float4*)(zs + d * 128 + 4 * tg);   // already 2*z
            float4 ea = *(const float4*)(e1 + d * KCODE);
            float4 eb = *(const float4*)(e2 + d * KCODE);
            float ev[8] = {ea.x, ea.y, ea.z, ea.w, eb.x, eb.y, eb.z, eb.w};
            #pragma unroll
            for (int c = 0; c < 8; c++) {
                m[0][c] = fmaf(zf.x, ev[c], m[0][c]);
                m[1][c] = fmaf(zf.y, ev[c], m[1][c]);
                m[2][c] = fmaf(zf.z, ev[c], m[2][c]);
                m[3][c] = fmaf(zf.w, ev[c], m[3][c]);
            }
        }
        float av[4] = {a0, a1, a2, a3};
        #pragma unroll
        for (int c = 0; c < 8; c++) {
            int k = pass * 128 + ((c < 4) ? (4 * cg + c) : (64 + 4 * cg + (c - 4)));
            float bk = Bs[k];
            #pragma unroll
            for (int t = 0; t < 4; t++) {
                float dd = __fsub_rn(__fadd_rn(av[t], bk), m[t][c]);
                // within-thread k sequence is ascending -> strict < = first index
                if (dd < best[t]) { best[t] = dd; bidx[t] = k; }
            }
        }
    }

    // lexicographic (dist, index) min across the 16 cg lanes (half-warp)
    #pragma unroll
    for (int off = 8; off >= 1; off >>= 1) {
        #pragma unroll
        for (int t = 0; t < 4; t++) {
            float od = __shfl_xor_sync(0xffffffffu, best[t], off);
            int oi = __shfl_xor_sync(0xffffffffu, bidx[t], off);
            if (od < best[t] || (od == best[t] && oi < bidx[t])) {
                best[t] = od; bidx[t] = oi;
            }
        }
    }

    if (cg == 0) {
        float ls = 0.f;
        #pragma unroll
        for (int t = 0; t < 4; t++) {
            size_t n = base + 4 * tg + t;
            g_idx[n] = bidx[t];
            atomicAdd(&g_counts[bidx[t]], 1u);
            ls += best[t];          // dist == ||z - e||^2 (loose tolerance)
        }
        lred[tg] = ls;
    }
    __syncthreads();
    if (tid == 0) {
        float acc = 0.f;
        #pragma unroll
        for (int t = 0; t < 32; t++) acc += lred[t];
        g_loss_part[blockIdx.x] = acc;
    }
}

// ---------------- gather: out[n][i] = table[idx[n]][i] ---------------------
__global__ void k_gather(float* __restrict__ out) {
    __shared__ int sidx[32];
    int tid = threadIdx.x;
    size_t base = (size_t)blockIdx.x * 32;
    if (tid < 32) sidx[tid] = g_idx[base + tid];
    __syncthreads();
    int rr = tid >> 6, q = tid & 63;
    #pragma unroll
    for (int j = 0; j < 8; j++) {
        int t = j * 4 + rr;
        float4 v = *(const float4*)(g_table + (size_t)sidx[t] * IN_DIM + 4 * q);
        float* o = out + (base + t) * IN_DIM + 4 * q;
        o[0] = v.x; o[1] = v.y; o[2] = v.z; o[3] = v.w;
    }
}

// ---------------- final: loss + perplexity ---------------------------------
__global__ void k_final(float* __restrict__ out, int out_size) {
    __shared__ float red[512];
    int tid = threadIdx.x;

    unsigned int cnt = g_counts[tid];
    float p = (float)cnt * (1.0f / (float)N_TOK);
    red[tid] = p * logf(p + 1e-10f);
    __syncthreads();
    for (int st = 256; st > 0; st >>= 1) {
        if (tid < st) red[tid] += red[tid + st];
        __syncthreads();
    }
    float ent = -red[0];
    __syncthreads();

    red[tid] = g_loss_part[tid];
    __syncthreads();
    for (int st = 256; st > 0; st >>= 1) {
        if (tid < st) red[tid] += red[tid + st];
        __syncthreads();
    }
    if (tid == 0) {
        out[0] = 1.25f * red[0] / (float)((size_t)N_TOK * DIM);
        out[out_size - 1] = expf(ent);
    }
}

// ---------------- launch ----------------
extern "C" void kernel_launch(void* const* d_in, const int* in_sizes, int n_in,
                              void* d_out, int out_size) {
    const float* x = nullptr;
    const float* enc_w = nullptr;
    const float* dec_w = nullptr;
    const float* cb = nullptr;
    for (int i = 0; i < n_in; i++) {
        const float* p = (const float*)d_in[i];
        int sz = in_sizes[i];
        if (sz == N_TOK * IN_DIM) x = p;
        else if (sz == KCODE * DIM) cb = p;
        else if (sz == IN_DIM * DIM) { if (!enc_w) enc_w = p; else dec_w = p; }
    }

    const int SM_ENC = (IN_DIM * DIM + 128 * XPC) * 4;                       // 100352
    const int SM_VQ  = (DIM * KCODE + DIM * 128 + KCODE + 128 + 32) * 4;     // ~166KB
    cudaFuncSetAttribute(k_enc, cudaFuncAttributeMaxDynamicSharedMemorySize, SM_ENC);
    cudaFuncSetAttribute(k_vq,  cudaFuncAttributeMaxDynamicSharedMemorySize, SM_VQ);

    float* out = (float*)d_out;

    k_setup<<<65, 256>>>(cb);
    k_table<<<512, 256>>>(cb, dec_w);
    k_enc<<<N_TOK / 128, 256, SM_ENC>>>(x, enc_w);
    k_vq<<<N_TOK / 128, 512, SM_VQ>>>();
    k_gather<<<N_TOK / 32, 256>>>(out + 1);
    k_final<<<1, 512>>>(out, out_size);
}